// round 1
// baseline (speedup 1.0000x reference)
#include <cuda_runtime.h>
#include <math.h>
#include <stdint.h>

#define D_MODEL 512
#define N_HEADS 8
#define DH 64
#define N_LAYERS 6
#define D_FF 2048
#define SEQ 512
#define BATCH 8
#define VOCAB 32000
#define NTOK (BATCH * SEQ)   /* 4096 */
#define NEGV (-1e9f)

// ---------------- scratch (device globals; no runtime allocation) ----------------
__device__ float g_x[NTOK * D_MODEL];
__device__ float g_y[NTOK * D_MODEL];
__device__ float g_q[NTOK * D_MODEL];
__device__ float g_k[NTOK * D_MODEL];
__device__ float g_v[NTOK * D_MODEL];
__device__ float g_t[NTOK * D_MODEL];
__device__ float g_ff[NTOK * D_FF];
__device__ float g_s[(size_t)BATCH * N_HEADS * SEQ * SEQ];

// ---------------- embedding + positional encoding ----------------
__global__ void embed_kernel(const int* __restrict__ tok, const float* __restrict__ emb,
                             float* __restrict__ out) {
    int row = blockIdx.x;            // b*SEQ + s
    int s = row % SEQ;
    int t = tok[row];
    const float scale = 22.627416997969522f;           // sqrt(512)
    const float c = -9.210340371976184f / 512.0f;      // -ln(10000)/512
    for (int d = threadIdx.x; d < D_MODEL; d += blockDim.x) {
        int i2 = d & ~1;
        float div = expf((float)i2 * c);
        float ang = (float)s * div;
        float pe = (d & 1) ? cosf(ang) : sinf(ang);
        out[row * D_MODEL + d] = emb[(size_t)t * D_MODEL + d] * scale + pe;
    }
}

// ---------------- generic SGEMM: C = A[MxK] @ W[KxN] + bias (+ReLU) ----------------
// block 256 threads, 64x64 tile, 4x4 per thread, BK=16. All dims divisible.
__global__ void sgemm_kernel(const float* __restrict__ A, const float* __restrict__ W,
                             const float* __restrict__ bias, float* __restrict__ C,
                             int M, int N, int K, int relu) {
    __shared__ float As[16][65];   // [k][m], padded
    __shared__ float Bs[16][64];   // [k][n]
    int tid = threadIdx.x;
    int bm = blockIdx.y * 64, bn = blockIdx.x * 64;
    int tx = tid & 15, ty = tid >> 4;

    float acc[4][4];
#pragma unroll
    for (int i = 0; i < 4; i++)
#pragma unroll
        for (int j = 0; j < 4; j++) acc[i][j] = 0.f;

    int am = tid >> 2, akq = (tid & 3) * 4;      // A: row, k-quad
    int bk = tid >> 4, bnq = (tid & 15) * 4;     // B: k, n-quad

    for (int k0 = 0; k0 < K; k0 += 16) {
        float4 av = *(const float4*)(A + (size_t)(bm + am) * K + k0 + akq);
        As[akq + 0][am] = av.x;
        As[akq + 1][am] = av.y;
        As[akq + 2][am] = av.z;
        As[akq + 3][am] = av.w;
        *(float4*)(&Bs[bk][bnq]) = *(const float4*)(W + (size_t)(k0 + bk) * N + bn + bnq);
        __syncthreads();
#pragma unroll
        for (int kk = 0; kk < 16; kk++) {
            float a[4], b[4];
#pragma unroll
            for (int i = 0; i < 4; i++) a[i] = As[kk][ty * 4 + i];
#pragma unroll
            for (int j = 0; j < 4; j++) b[j] = Bs[kk][tx * 4 + j];
#pragma unroll
            for (int i = 0; i < 4; i++)
#pragma unroll
                for (int j = 0; j < 4; j++) acc[i][j] += a[i] * b[j];
        }
        __syncthreads();
    }

#pragma unroll
    for (int i = 0; i < 4; i++) {
        int m = bm + ty * 4 + i;
#pragma unroll
        for (int j = 0; j < 4; j++) {
            int n = bn + tx * 4 + j;
            float v = acc[i][j] + bias[n];
            if (relu) v = fmaxf(v, 0.f);
            C[(size_t)m * N + n] = v;
        }
    }
}

// ---------------- attention scores: S = QK^T/8 with mask ----------------
// grid (SEQ/32 [i], SEQ/32 [j], B*H), block 256
__global__ void attn_score_kernel(const float* __restrict__ Q, const float* __restrict__ Kt,
                                  const int* __restrict__ src_tok,  // non-null: key-pad mask
                                  const int* __restrict__ tgt_tok,  // non-null: causal+query-pad
                                  float* __restrict__ S) {
    int bh = blockIdx.z;
    int b = bh >> 3, h = bh & 7;
    int i0 = blockIdx.x * 32, j0 = blockIdx.y * 32;
    __shared__ float qs[32][68];
    __shared__ float ks[32][68];
    int tid = threadIdx.x;
    const float* qbase = Q + ((size_t)(b * SEQ + i0)) * D_MODEL + h * DH;
    const float* kbase = Kt + ((size_t)(b * SEQ + j0)) * D_MODEL + h * DH;
    for (int e = tid; e < 512; e += 256) {  // 512 float4 per tile
        int r = e >> 4, c4 = (e & 15) * 4;
        *(float4*)&qs[r][c4] = *(const float4*)(qbase + (size_t)r * D_MODEL + c4);
        *(float4*)&ks[r][c4] = *(const float4*)(kbase + (size_t)r * D_MODEL + c4);
    }
    __syncthreads();

    int ii = tid >> 3;
    int jj0 = (tid & 7) * 4;
    float acc[4] = {0.f, 0.f, 0.f, 0.f};
#pragma unroll
    for (int d = 0; d < DH; d++) {
        float qv = qs[ii][d];
        acc[0] += qv * ks[jj0 + 0][d];
        acc[1] += qv * ks[jj0 + 1][d];
        acc[2] += qv * ks[jj0 + 2][d];
        acc[3] += qv * ks[jj0 + 3][d];
    }
    int i = i0 + ii;
    float* srow = S + (((size_t)bh * SEQ + i) * SEQ);
    bool qvalid = true;
    if (tgt_tok) qvalid = (tgt_tok[b * SEQ + i] != 0);
#pragma unroll
    for (int j4 = 0; j4 < 4; j4++) {
        int j = j0 + jj0 + j4;
        bool valid;
        if (src_tok)
            valid = (src_tok[b * SEQ + j] != 0);
        else
            valid = qvalid && (j <= i);
        srow[j] = valid ? acc[j4] * 0.125f : NEGV;
    }
}

// ---------------- softmax over last dim (row = 512) ----------------
__global__ void softmax_kernel(float* __restrict__ S) {
    size_t row = blockIdx.x;
    float* p = S + row * SEQ;
    int tid = threadIdx.x;
    float v0 = p[tid], v1 = p[tid + 256];
    __shared__ float red[8];
    float m = fmaxf(v0, v1);
#pragma unroll
    for (int o = 16; o; o >>= 1) m = fmaxf(m, __shfl_xor_sync(0xffffffffu, m, o));
    if ((tid & 31) == 0) red[tid >> 5] = m;
    __syncthreads();
    float mm = red[0];
#pragma unroll
    for (int i = 1; i < 8; i++) mm = fmaxf(mm, red[i]);
    __syncthreads();
    float e0 = expf(v0 - mm), e1 = expf(v1 - mm);
    float ssum = e0 + e1;
#pragma unroll
    for (int o = 16; o; o >>= 1) ssum += __shfl_xor_sync(0xffffffffu, ssum, o);
    if ((tid & 31) == 0) red[tid >> 5] = ssum;
    __syncthreads();
    float tot = red[0];
#pragma unroll
    for (int i = 1; i < 8; i++) tot += red[i];
    float inv = 1.0f / tot;
    p[tid] = e0 * inv;
    p[tid + 256] = e1 * inv;
}

// ---------------- O = P @ V (per head), out laid out [B,S,H,DH] ----------------
// grid (SEQ/32 [i], B*H), block 256
__global__ void attn_av_kernel(const float* __restrict__ P, const float* __restrict__ V,
                               float* __restrict__ O) {
    int bh = blockIdx.y;
    int b = bh >> 3, h = bh & 7;
    int i0 = blockIdx.x * 32;
    __shared__ float ps[32][36];
    __shared__ float vs[32][68];
    int tid = threadIdx.x;
    int ii = tid >> 3;
    int d0 = (tid & 7) * 8;
    float acc[8];
#pragma unroll
    for (int x = 0; x < 8; x++) acc[x] = 0.f;
    const float* pbase = P + ((size_t)bh * SEQ + i0) * SEQ;
    int pr = tid >> 3, pc4 = (tid & 7) * 4;
    for (int j0 = 0; j0 < SEQ; j0 += 32) {
        *(float4*)&ps[pr][pc4] = *(const float4*)(pbase + (size_t)pr * SEQ + j0 + pc4);
        const float* vbase = V + ((size_t)(b * SEQ + j0)) * D_MODEL + h * DH;
        for (int e = tid; e < 512; e += 256) {
            int vr = e >> 4, vc4 = (e & 15) * 4;
            *(float4*)&vs[vr][vc4] = *(const float4*)(vbase + (size_t)vr * D_MODEL + vc4);
        }
        __syncthreads();
#pragma unroll
        for (int jj = 0; jj < 32; jj++) {
            float pv = ps[ii][jj];
#pragma unroll
            for (int x = 0; x < 8; x++) acc[x] += pv * vs[jj][d0 + x];
        }
        __syncthreads();
    }
    float* obase = O + ((size_t)(b * SEQ + i0 + ii)) * D_MODEL + h * DH + d0;
#pragma unroll
    for (int x = 0; x < 8; x++) obase[x] = acc[x];
}

// ---------------- fused residual-add + LayerNorm (row = 512) ----------------
// out = LN(A + R) * s + b ;  out may alias R (row-local)
__global__ void ln_kernel(const float* __restrict__ A, const float* __restrict__ R,
                          const float* __restrict__ sc, const float* __restrict__ bi,
                          float* __restrict__ out) {
    int row = blockIdx.x, tid = threadIdx.x;
    size_t base = (size_t)row * D_MODEL;
    float x0 = A[base + tid] + R[base + tid];
    float x1 = A[base + tid + 256] + R[base + tid + 256];
    __shared__ float red[8];
    float ssum = x0 + x1;
#pragma unroll
    for (int o = 16; o; o >>= 1) ssum += __shfl_xor_sync(0xffffffffu, ssum, o);
    if ((tid & 31) == 0) red[tid >> 5] = ssum;
    __syncthreads();
    float tot = red[0];
#pragma unroll
    for (int i = 1; i < 8; i++) tot += red[i];
    float mean = tot * (1.0f / D_MODEL);
    __syncthreads();
    float d0 = x0 - mean, d1 = x1 - mean;
    float vsum = d0 * d0 + d1 * d1;
#pragma unroll
    for (int o = 16; o; o >>= 1) vsum += __shfl_xor_sync(0xffffffffu, vsum, o);
    if ((tid & 31) == 0) red[tid >> 5] = vsum;
    __syncthreads();
    float vtot = red[0];
#pragma unroll
    for (int i = 1; i < 8; i++) vtot += red[i];
    float inv = rsqrtf(vtot * (1.0f / D_MODEL) + 1e-5f);
    out[base + tid] = d0 * inv * sc[tid] + bi[tid];
    out[base + tid + 256] = d1 * inv * sc[tid + 256] + bi[tid + 256];
}

// ---------------- host orchestration ----------------
static inline void gemm(const float* A, const float* W, const float* bias, float* C,
                        int M, int N, int K, int relu) {
    dim3 grid(N / 64, M / 64);
    sgemm_kernel<<<grid, 256>>>(A, W, bias, C, M, N, K, relu);
}

extern "C" void kernel_launch(void* const* d_in, const int* in_sizes, int n_in,
                              void* d_out, int out_size) {
    const int* src = (const int*)d_in[0];
    const int* tgt = (const int*)d_in[1];
    const float* src_emb = (const float*)d_in[2];
    const float* tgt_emb = (const float*)d_in[3];
    const float* enc_attn_w = (const float*)d_in[4];
    const float* enc_attn_b = (const float*)d_in[5];
    const float* enc_ln_s = (const float*)d_in[6];
    const float* enc_ln_b = (const float*)d_in[7];
    const float* enc_ff_w1 = (const float*)d_in[8];
    const float* enc_ff_b1 = (const float*)d_in[9];
    const float* enc_ff_w2 = (const float*)d_in[10];
    const float* enc_ff_b2 = (const float*)d_in[11];
    const float* dec_attn_w = (const float*)d_in[12];
    const float* dec_attn_b = (const float*)d_in[13];
    const float* dec_ln_s = (const float*)d_in[14];
    const float* dec_ln_b = (const float*)d_in[15];
    const float* dec_ff_w1 = (const float*)d_in[16];
    const float* dec_ff_b1 = (const float*)d_in[17];
    const float* dec_ff_w2 = (const float*)d_in[18];
    const float* dec_ff_b2 = (const float*)d_in[19];
    const float* fc_w = (const float*)d_in[20];
    const float* fc_b = (const float*)d_in[21];
    float* out = (float*)d_out;

    float *x, *y, *q, *k, *v, *t, *ff, *s;
    cudaGetSymbolAddress((void**)&x, g_x);
    cudaGetSymbolAddress((void**)&y, g_y);
    cudaGetSymbolAddress((void**)&q, g_q);
    cudaGetSymbolAddress((void**)&k, g_k);
    cudaGetSymbolAddress((void**)&v, g_v);
    cudaGetSymbolAddress((void**)&t, g_t);
    cudaGetSymbolAddress((void**)&ff, g_ff);
    cudaGetSymbolAddress((void**)&s, g_s);

    const dim3 sc_grid(SEQ / 32, SEQ / 32, BATCH * N_HEADS);
    const dim3 av_grid(SEQ / 32, BATCH * N_HEADS);
    const int sm_grid = BATCH * N_HEADS * SEQ;
    const size_t WSZ = (size_t)D_MODEL * D_MODEL;

    // ---------------- encoder ----------------
    embed_kernel<<<NTOK, 256>>>(src, src_emb, x);
    for (int l = 0; l < N_LAYERS; l++) {
        const float* W = enc_attn_w + (size_t)l * 4 * WSZ;
        const float* Bv = enc_attn_b + (size_t)l * 4 * D_MODEL;
        gemm(x, W + 0 * WSZ, Bv + 0 * D_MODEL, q, NTOK, D_MODEL, D_MODEL, 0);
        gemm(x, W + 1 * WSZ, Bv + 1 * D_MODEL, k, NTOK, D_MODEL, D_MODEL, 0);
        gemm(x, W + 2 * WSZ, Bv + 2 * D_MODEL, v, NTOK, D_MODEL, D_MODEL, 0);
        attn_score_kernel<<<sc_grid, 256>>>(q, k, src, nullptr, s);
        softmax_kernel<<<sm_grid, 256>>>(s);
        attn_av_kernel<<<av_grid, 256>>>(s, v, t);
        gemm(t, W + 3 * WSZ, Bv + 3 * D_MODEL, q, NTOK, D_MODEL, D_MODEL, 0);
        ln_kernel<<<NTOK, 256>>>(q, x, enc_ln_s + (size_t)(l * 2 + 0) * D_MODEL,
                                 enc_ln_b + (size_t)(l * 2 + 0) * D_MODEL, x);
        gemm(x, enc_ff_w1 + (size_t)l * D_MODEL * D_FF, enc_ff_b1 + (size_t)l * D_FF, ff,
             NTOK, D_FF, D_MODEL, 1);
        gemm(ff, enc_ff_w2 + (size_t)l * D_FF * D_MODEL, enc_ff_b2 + (size_t)l * D_MODEL, t,
             NTOK, D_MODEL, D_FF, 0);
        ln_kernel<<<NTOK, 256>>>(t, x, enc_ln_s + (size_t)(l * 2 + 1) * D_MODEL,
                                 enc_ln_b + (size_t)(l * 2 + 1) * D_MODEL, x);
    }

    // ---------------- decoder ----------------
    embed_kernel<<<NTOK, 256>>>(tgt, tgt_emb, y);
    for (int l = 0; l < N_LAYERS; l++) {
        const float* W = dec_attn_w + (size_t)l * 8 * WSZ;
        const float* Bv = dec_attn_b + (size_t)l * 8 * D_MODEL;
        const float* lns = dec_ln_s + (size_t)l * 3 * D_MODEL;
        const float* lnb = dec_ln_b + (size_t)l * 3 * D_MODEL;
        // self-attn (causal + tgt pad)
        gemm(y, W + 0 * WSZ, Bv + 0 * D_MODEL, q, NTOK, D_MODEL, D_MODEL, 0);
        gemm(y, W + 1 * WSZ, Bv + 1 * D_MODEL, k, NTOK, D_MODEL, D_MODEL, 0);
        gemm(y, W + 2 * WSZ, Bv + 2 * D_MODEL, v, NTOK, D_MODEL, D_MODEL, 0);
        attn_score_kernel<<<sc_grid, 256>>>(q, k, nullptr, tgt, s);
        softmax_kernel<<<sm_grid, 256>>>(s);
        attn_av_kernel<<<av_grid, 256>>>(s, v, t);
        gemm(t, W + 3 * WSZ, Bv + 3 * D_MODEL, q, NTOK, D_MODEL, D_MODEL, 0);
        ln_kernel<<<NTOK, 256>>>(q, y, lns + 0 * D_MODEL, lnb + 0 * D_MODEL, y);
        // cross-attn (keys/values from encoder output x)
        gemm(y, W + 4 * WSZ, Bv + 4 * D_MODEL, q, NTOK, D_MODEL, D_MODEL, 0);
        gemm(x, W + 5 * WSZ, Bv + 5 * D_MODEL, k, NTOK, D_MODEL, D_MODEL, 0);
        gemm(x, W + 6 * WSZ, Bv + 6 * D_MODEL, v, NTOK, D_MODEL, D_MODEL, 0);
        attn_score_kernel<<<sc_grid, 256>>>(q, k, src, nullptr, s);
        softmax_kernel<<<sm_grid, 256>>>(s);
        attn_av_kernel<<<av_grid, 256>>>(s, v, t);
        gemm(t, W + 7 * WSZ, Bv + 7 * D_MODEL, q, NTOK, D_MODEL, D_MODEL, 0);
        ln_kernel<<<NTOK, 256>>>(q, y, lns + 1 * D_MODEL, lnb + 1 * D_MODEL, y);
        // ffn
        gemm(y, dec_ff_w1 + (size_t)l * D_MODEL * D_FF, dec_ff_b1 + (size_t)l * D_FF, ff,
             NTOK, D_FF, D_MODEL, 1);
        gemm(ff, dec_ff_w2 + (size_t)l * D_FF * D_MODEL, dec_ff_b2 + (size_t)l * D_MODEL, t,
             NTOK, D_MODEL, D_FF, 0);
        ln_kernel<<<NTOK, 256>>>(t, y, lns + 2 * D_MODEL, lnb + 2 * D_MODEL, y);
    }

    // ---------------- final projection ----------------
    gemm(y, fc_w, fc_b, out, NTOK, VOCAB, D_MODEL, 0);
}

// round 3
// speedup vs baseline: 1.3779x; 1.3779x over previous
#include <cuda_runtime.h>
#include <cuda_bf16.h>
#include <math.h>
#include <stdint.h>

#define D_MODEL 512
#define N_HEADS 8
#define DH 64
#define N_LAYERS 6
#define D_FF 2048
#define SEQ 512
#define BATCH 8
#define VOCAB 32000
#define NTOK (BATCH * SEQ)   /* 4096 */
#define NEGV (-1e9f)

// ---------------- scratch (device globals; no runtime allocation) ----------------
__device__ float g_x[NTOK * D_MODEL];
__device__ float g_y[NTOK * D_MODEL];
__device__ float g_q[NTOK * D_MODEL];
__device__ float g_k[NTOK * D_MODEL];
__device__ float g_v[NTOK * D_MODEL];
__device__ float g_t[NTOK * D_MODEL];
__device__ float g_ff[NTOK * D_FF];
__device__ float g_s[(size_t)BATCH * N_HEADS * SEQ * SEQ];

// =================== HMMA bf16 helpers ===================
__device__ __forceinline__ void mma_bf16(float& d0, float& d1, float& d2, float& d3,
                                         uint32_t a0, uint32_t a1, uint32_t a2, uint32_t a3,
                                         uint32_t b0, uint32_t b1) {
    asm volatile(
        "mma.sync.aligned.m16n8k16.row.col.f32.bf16.bf16.f32 "
        "{%0,%1,%2,%3}, {%4,%5,%6,%7}, {%8,%9}, {%0,%1,%2,%3};\n"
        : "+f"(d0), "+f"(d1), "+f"(d2), "+f"(d3)
        : "r"(a0), "r"(a1), "r"(a2), "r"(a3), "r"(b0), "r"(b1));
}

// split x,y into bf16 hi pair (returned) and lo pair (out param)
__device__ __forceinline__ uint32_t bf16x3_pack(float x, float y, uint32_t& lo) {
    __nv_bfloat16 hx = __float2bfloat16(x), hy = __float2bfloat16(y);
    __nv_bfloat16 lx = __float2bfloat16(x - __bfloat162float(hx));
    __nv_bfloat16 ly = __float2bfloat16(y - __bfloat162float(hy));
    lo = ((uint32_t)__bfloat16_as_ushort(ly) << 16) | (uint32_t)__bfloat16_as_ushort(lx);
    return ((uint32_t)__bfloat16_as_ushort(hy) << 16) | (uint32_t)__bfloat16_as_ushort(hx);
}

// =================== HMMA GEMM: C = A[MxK] @ W[KxN] + bias (+ReLU) ===================
// fp32 in/out, bf16x3 split internally. CTA 128x128, BK=32, 8 warps (warp tile 32x64).
#define BM 128
#define BN 128
#define BK 32
#define STRA 40   /* halves per A smem row (k) */
#define STRB 34   /* halves per B smem row (k), B stored [n][k] */

__global__ __launch_bounds__(256, 2) void hmma_gemm_kernel(
    const float* __restrict__ A, const float* __restrict__ W,
    const float* __restrict__ bias, float* __restrict__ C,
    int M, int N, int K, int relu) {
    __shared__ __nv_bfloat16 sA_hi[BM * STRA];
    __shared__ __nv_bfloat16 sA_lo[BM * STRA];
    __shared__ __nv_bfloat16 sB_hi[BN * STRB];
    __shared__ __nv_bfloat16 sB_lo[BN * STRB];

    int tid = threadIdx.x, lane = tid & 31, w = tid >> 5;
    int wm = (w & 3) * 32, wn = (w >> 2) * 64;
    int g = lane >> 2, t = lane & 3;
    int bm = blockIdx.y * BM, bn = blockIdx.x * BN;

    float d[2][8][4];
#pragma unroll
    for (int mt = 0; mt < 2; mt++)
#pragma unroll
        for (int nt = 0; nt < 8; nt++)
#pragma unroll
            for (int e = 0; e < 4; e++) d[mt][nt][e] = 0.f;

    for (int kc = 0; kc < K; kc += BK) {
        // ---- stage A tile [128 m][32 k], split hi/lo ----
#pragma unroll
        for (int i = 0; i < 4; i++) {
            int idx = i * 256 + tid;
            int r = idx >> 3, q = idx & 7;           // 8 float4 per row
            float4 v = *(const float4*)(A + (size_t)(bm + r) * K + kc + q * 4);
            uint32_t lo0, lo1;
            uint32_t hi0 = bf16x3_pack(v.x, v.y, lo0);
            uint32_t hi1 = bf16x3_pack(v.z, v.w, lo1);
            uint32_t* ph = (uint32_t*)&sA_hi[r * STRA + q * 4];
            uint32_t* pl = (uint32_t*)&sA_lo[r * STRA + q * 4];
            ph[0] = hi0; ph[1] = hi1;
            pl[0] = lo0; pl[1] = lo1;
        }
        // ---- stage B tile transposed: W[K,N] -> sB[n][k], k-paired b32 stores ----
#pragma unroll
        for (int it = 0; it < 2; it++) {
            int idx = it * 256 + tid;
            int kp = idx >> 5;                 // k-pair 0..15
            int nq = (idx & 31) * 4;           // n quad
            const float* w0 = W + (size_t)(kc + 2 * kp) * N + bn + nq;
            float4 v0 = *(const float4*)w0;
            float4 v1 = *(const float4*)(w0 + N);
            float x0[4] = {v0.x, v0.y, v0.z, v0.w};
            float x1[4] = {v1.x, v1.y, v1.z, v1.w};
#pragma unroll
            for (int j = 0; j < 4; j++) {
                uint32_t lo;
                uint32_t hi = bf16x3_pack(x0[j], x1[j], lo);  // (k, k+1) for row n=nq+j
                *(uint32_t*)&sB_hi[(nq + j) * STRB + 2 * kp] = hi;
                *(uint32_t*)&sB_lo[(nq + j) * STRB + 2 * kp] = lo;
            }
        }
        __syncthreads();

#pragma unroll
        for (int ks = 0; ks < 2; ks++) {
            int k0 = ks * 16;
            uint32_t ah[2][4], al[2][4];
#pragma unroll
            for (int mt = 0; mt < 2; mt++) {
                int row = wm + mt * 16 + g;
                const __nv_bfloat16* pa = &sA_hi[row * STRA + k0 + 2 * t];
                ah[mt][0] = *(const uint32_t*)pa;
                ah[mt][1] = *(const uint32_t*)(pa + 8 * STRA);
                ah[mt][2] = *(const uint32_t*)(pa + 8);
                ah[mt][3] = *(const uint32_t*)(pa + 8 * STRA + 8);
                const __nv_bfloat16* pl = &sA_lo[row * STRA + k0 + 2 * t];
                al[mt][0] = *(const uint32_t*)pl;
                al[mt][1] = *(const uint32_t*)(pl + 8 * STRA);
                al[mt][2] = *(const uint32_t*)(pl + 8);
                al[mt][3] = *(const uint32_t*)(pl + 8 * STRA + 8);
            }
#pragma unroll
            for (int nt = 0; nt < 8; nt++) {
                int col = wn + nt * 8 + g;
                const __nv_bfloat16* pb = &sB_hi[col * STRB + k0 + 2 * t];
                uint32_t bh0 = *(const uint32_t*)pb;
                uint32_t bh1 = *(const uint32_t*)(pb + 8);
                const __nv_bfloat16* pbl = &sB_lo[col * STRB + k0 + 2 * t];
                uint32_t bl0 = *(const uint32_t*)pbl;
                uint32_t bl1 = *(const uint32_t*)(pbl + 8);
#pragma unroll
                for (int mt = 0; mt < 2; mt++) {
                    mma_bf16(d[mt][nt][0], d[mt][nt][1], d[mt][nt][2], d[mt][nt][3],
                             ah[mt][0], ah[mt][1], ah[mt][2], ah[mt][3], bh0, bh1);
                    mma_bf16(d[mt][nt][0], d[mt][nt][1], d[mt][nt][2], d[mt][nt][3],
                             ah[mt][0], ah[mt][1], ah[mt][2], ah[mt][3], bl0, bl1);
                    mma_bf16(d[mt][nt][0], d[mt][nt][1], d[mt][nt][2], d[mt][nt][3],
                             al[mt][0], al[mt][1], al[mt][2], al[mt][3], bh0, bh1);
                }
            }
        }
        __syncthreads();
    }

    // ---- epilogue: registers -> gmem, +bias (+relu) ----
#pragma unroll
    for (int mt = 0; mt < 2; mt++) {
        int r0 = bm + wm + mt * 16 + g;
#pragma unroll
        for (int nt = 0; nt < 8; nt++) {
            int col = bn + wn + nt * 8 + 2 * t;
            float b0 = bias[col], b1 = bias[col + 1];
            float v0 = d[mt][nt][0] + b0, v1 = d[mt][nt][1] + b1;
            float v2 = d[mt][nt][2] + b0, v3 = d[mt][nt][3] + b1;
            if (relu) {
                v0 = fmaxf(v0, 0.f); v1 = fmaxf(v1, 0.f);
                v2 = fmaxf(v2, 0.f); v3 = fmaxf(v3, 0.f);
            }
            *(float2*)(C + (size_t)r0 * N + col) = make_float2(v0, v1);
            *(float2*)(C + (size_t)(r0 + 8) * N + col) = make_float2(v2, v3);
        }
    }
}

// ---------------- embedding + positional encoding ----------------
__global__ void embed_kernel(const int* __restrict__ tok, const float* __restrict__ emb,
                             float* __restrict__ out) {
    int row = blockIdx.x;
    int s = row % SEQ;
    int t = tok[row];
    const float scale = 22.627416997969522f;
    const float c = -9.210340371976184f / 512.0f;
    for (int d = threadIdx.x; d < D_MODEL; d += blockDim.x) {
        int i2 = d & ~1;
        float div = expf((float)i2 * c);
        float ang = (float)s * div;
        float pe = (d & 1) ? cosf(ang) : sinf(ang);
        out[row * D_MODEL + d] = emb[(size_t)t * D_MODEL + d] * scale + pe;
    }
}

// ---------------- attention scores: S = QK^T/8 with mask ----------------
__global__ void attn_score_kernel(const float* __restrict__ Q, const float* __restrict__ Kt,
                                  const int* __restrict__ src_tok,
                                  const int* __restrict__ tgt_tok,
                                  float* __restrict__ S) {
    int bh = blockIdx.z;
    int b = bh >> 3, h = bh & 7;
    int i0 = blockIdx.x * 32, j0 = blockIdx.y * 32;
    __shared__ float qs[32][68];
    __shared__ float ks[32][68];
    int tid = threadIdx.x;
    const float* qbase = Q + ((size_t)(b * SEQ + i0)) * D_MODEL + h * DH;
    const float* kbase = Kt + ((size_t)(b * SEQ + j0)) * D_MODEL + h * DH;
    for (int e = tid; e < 512; e += 256) {
        int r = e >> 4, c4 = (e & 15) * 4;
        *(float4*)&qs[r][c4] = *(const float4*)(qbase + (size_t)r * D_MODEL + c4);
        *(float4*)&ks[r][c4] = *(const float4*)(kbase + (size_t)r * D_MODEL + c4);
    }
    __syncthreads();

    int ii = tid >> 3;
    int jj0 = (tid & 7) * 4;
    float acc[4] = {0.f, 0.f, 0.f, 0.f};
#pragma unroll
    for (int d = 0; d < DH; d++) {
        float qv = qs[ii][d];
        acc[0] += qv * ks[jj0 + 0][d];
        acc[1] += qv * ks[jj0 + 1][d];
        acc[2] += qv * ks[jj0 + 2][d];
        acc[3] += qv * ks[jj0 + 3][d];
    }
    int i = i0 + ii;
    float* srow = S + (((size_t)bh * SEQ + i) * SEQ);
    bool qvalid = true;
    if (tgt_tok) qvalid = (tgt_tok[b * SEQ + i] != 0);
#pragma unroll
    for (int j4 = 0; j4 < 4; j4++) {
        int j = j0 + jj0 + j4;
        bool valid;
        if (src_tok)
            valid = (src_tok[b * SEQ + j] != 0);
        else
            valid = qvalid && (j <= i);
        srow[j] = valid ? acc[j4] * 0.125f : NEGV;
    }
}

// ---------------- softmax over last dim (row = 512) ----------------
__global__ void softmax_kernel(float* __restrict__ S) {
    size_t row = blockIdx.x;
    float* p = S + row * SEQ;
    int tid = threadIdx.x;
    float v0 = p[tid], v1 = p[tid + 256];
    __shared__ float red[8];
    float m = fmaxf(v0, v1);
#pragma unroll
    for (int o = 16; o; o >>= 1) m = fmaxf(m, __shfl_xor_sync(0xffffffffu, m, o));
    if ((tid & 31) == 0) red[tid >> 5] = m;
    __syncthreads();
    float mm = red[0];
#pragma unroll
    for (int i = 1; i < 8; i++) mm = fmaxf(mm, red[i]);
    __syncthreads();
    float e0 = expf(v0 - mm), e1 = expf(v1 - mm);
    float ssum = e0 + e1;
#pragma unroll
    for (int o = 16; o; o >>= 1) ssum += __shfl_xor_sync(0xffffffffu, ssum, o);
    if ((tid & 31) == 0) red[tid >> 5] = ssum;
    __syncthreads();
    float tot = red[0];
#pragma unroll
    for (int i = 1; i < 8; i++) tot += red[i];
    float inv = 1.0f / tot;
    p[tid] = e0 * inv;
    p[tid + 256] = e1 * inv;
}

// ---------------- O = P @ V (per head) ----------------
__global__ void attn_av_kernel(const float* __restrict__ P, const float* __restrict__ V,
                               float* __restrict__ O) {
    int bh = blockIdx.y;
    int b = bh >> 3, h = bh & 7;
    int i0 = blockIdx.x * 32;
    __shared__ float ps[32][36];
    __shared__ float vs[32][68];
    int tid = threadIdx.x;
    int ii = tid >> 3;
    int d0 = (tid & 7) * 8;
    float acc[8];
#pragma unroll
    for (int x = 0; x < 8; x++) acc[x] = 0.f;
    const float* pbase = P + ((size_t)bh * SEQ + i0) * SEQ;
    int pr = tid >> 3, pc4 = (tid & 7) * 4;
    for (int j0 = 0; j0 < SEQ; j0 += 32) {
        *(float4*)&ps[pr][pc4] = *(const float4*)(pbase + (size_t)pr * SEQ + j0 + pc4);
        const float* vbase = V + ((size_t)(b * SEQ + j0)) * D_MODEL + h * DH;
        for (int e = tid; e < 512; e += 256) {
            int vr = e >> 4, vc4 = (e & 15) * 4;
            *(float4*)&vs[vr][vc4] = *(const float4*)(vbase + (size_t)vr * D_MODEL + vc4);
        }
        __syncthreads();
#pragma unroll
        for (int jj = 0; jj < 32; jj++) {
            float pv = ps[ii][jj];
#pragma unroll
            for (int x = 0; x < 8; x++) acc[x] += pv * vs[jj][d0 + x];
        }
        __syncthreads();
    }
    float* obase = O + ((size_t)(b * SEQ + i0 + ii)) * D_MODEL + h * DH + d0;
#pragma unroll
    for (int x = 0; x < 8; x++) obase[x] = acc[x];
}

// ---------------- fused residual-add + LayerNorm ----------------
__global__ void ln_kernel(const float* __restrict__ A, const float* __restrict__ R,
                          const float* __restrict__ sc, const float* __restrict__ bi,
                          float* __restrict__ out) {
    int row = blockIdx.x, tid = threadIdx.x;
    size_t base = (size_t)row * D_MODEL;
    float x0 = A[base + tid] + R[base + tid];
    float x1 = A[base + tid + 256] + R[base + tid + 256];
    __shared__ float red[8];
    float ssum = x0 + x1;
#pragma unroll
    for (int o = 16; o; o >>= 1) ssum += __shfl_xor_sync(0xffffffffu, ssum, o);
    if ((tid & 31) == 0) red[tid >> 5] = ssum;
    __syncthreads();
    float tot = red[0];
#pragma unroll
    for (int i = 1; i < 8; i++) tot += red[i];
    float mean = tot * (1.0f / D_MODEL);
    __syncthreads();
    float d0 = x0 - mean, d1 = x1 - mean;
    float vsum = d0 * d0 + d1 * d1;
#pragma unroll
    for (int o = 16; o; o >>= 1) vsum += __shfl_xor_sync(0xffffffffu, vsum, o);
    if ((tid & 31) == 0) red[tid >> 5] = vsum;
    __syncthreads();
    float vtot = red[0];
#pragma unroll
    for (int i = 1; i < 8; i++) vtot += red[i];
    float inv = rsqrtf(vtot * (1.0f / D_MODEL) + 1e-5f);
    out[base + tid] = d0 * inv * sc[tid] + bi[tid];
    out[base + tid + 256] = d1 * inv * sc[tid + 256] + bi[tid + 256];
}

// ---------------- host orchestration ----------------
static inline void gemm(const float* A, const float* W, const float* bias, float* C,
                        int M, int N, int K, int relu) {
    dim3 grid(N / BN, M / BM);
    hmma_gemm_kernel<<<grid, 256>>>(A, W, bias, C, M, N, K, relu);
}

extern "C" void kernel_launch(void* const* d_in, const int* in_sizes, int n_in,
                              void* d_out, int out_size) {
    const int* src = (const int*)d_in[0];
    const int* tgt = (const int*)d_in[1];
    const float* src_emb = (const float*)d_in[2];
    const float* tgt_emb = (const float*)d_in[3];
    const float* enc_attn_w = (const float*)d_in[4];
    const float* enc_attn_b = (const float*)d_in[5];
    const float* enc_ln_s = (const float*)d_in[6];
    const float* enc_ln_b = (const float*)d_in[7];
    const float* enc_ff_w1 = (const float*)d_in[8];
    const float* enc_ff_b1 = (const float*)d_in[9];
    const float* enc_ff_w2 = (const float*)d_in[10];
    const float* enc_ff_b2 = (const float*)d_in[11];
    const float* dec_attn_w = (const float*)d_in[12];
    const float* dec_attn_b = (const float*)d_in[13];
    const float* dec_ln_s = (const float*)d_in[14];
    const float* dec_ln_b = (const float*)d_in[15];
    const float* dec_ff_w1 = (const float*)d_in[16];
    const float* dec_ff_b1 = (const float*)d_in[17];
    const float* dec_ff_w2 = (const float*)d_in[18];
    const float* dec_ff_b2 = (const float*)d_in[19];
    const float* fc_w = (const float*)d_in[20];
    const float* fc_b = (const float*)d_in[21];
    float* out = (float*)d_out;

    float *x, *y, *q, *k, *v, *t, *ff, *s;
    cudaGetSymbolAddress((void**)&x, g_x);
    cudaGetSymbolAddress((void**)&y, g_y);
    cudaGetSymbolAddress((void**)&q, g_q);
    cudaGetSymbolAddress((void**)&k, g_k);
    cudaGetSymbolAddress((void**)&v, g_v);
    cudaGetSymbolAddress((void**)&t, g_t);
    cudaGetSymbolAddress((void**)&ff, g_ff);
    cudaGetSymbolAddress((void**)&s, g_s);

    const dim3 sc_grid(SEQ / 32, SEQ / 32, BATCH * N_HEADS);
    const dim3 av_grid(SEQ / 32, BATCH * N_HEADS);
    const int sm_grid = BATCH * N_HEADS * SEQ;
    const size_t WSZ = (size_t)D_MODEL * D_MODEL;

    // ---------------- encoder ----------------
    embed_kernel<<<NTOK, 256>>>(src, src_emb, x);
    for (int l = 0; l < N_LAYERS; l++) {
        const float* W = enc_attn_w + (size_t)l * 4 * WSZ;
        const float* Bv = enc_attn_b + (size_t)l * 4 * D_MODEL;
        gemm(x, W + 0 * WSZ, Bv + 0 * D_MODEL, q, NTOK, D_MODEL, D_MODEL, 0);
        gemm(x, W + 1 * WSZ, Bv + 1 * D_MODEL, k, NTOK, D_MODEL, D_MODEL, 0);
        gemm(x, W + 2 * WSZ, Bv + 2 * D_MODEL, v, NTOK, D_MODEL, D_MODEL, 0);
        attn_score_kernel<<<sc_grid, 256>>>(q, k, src, nullptr, s);
        softmax_kernel<<<sm_grid, 256>>>(s);
        attn_av_kernel<<<av_grid, 256>>>(s, v, t);
        gemm(t, W + 3 * WSZ, Bv + 3 * D_MODEL, q, NTOK, D_MODEL, D_MODEL, 0);
        ln_kernel<<<NTOK, 256>>>(q, x, enc_ln_s + (size_t)(l * 2 + 0) * D_MODEL,
                                 enc_ln_b + (size_t)(l * 2 + 0) * D_MODEL, x);
        gemm(x, enc_ff_w1 + (size_t)l * D_MODEL * D_FF, enc_ff_b1 + (size_t)l * D_FF, ff,
             NTOK, D_FF, D_MODEL, 1);
        gemm(ff, enc_ff_w2 + (size_t)l * D_FF * D_MODEL, enc_ff_b2 + (size_t)l * D_MODEL, t,
             NTOK, D_MODEL, D_FF, 0);
        ln_kernel<<<NTOK, 256>>>(t, x, enc_ln_s + (size_t)(l * 2 + 1) * D_MODEL,
                                 enc_ln_b + (size_t)(l * 2 + 1) * D_MODEL, x);
    }

    // ---------------- decoder ----------------
    embed_kernel<<<NTOK, 256>>>(tgt, tgt_emb, y);
    for (int l = 0; l < N_LAYERS; l++) {
        const float* W = dec_attn_w + (size_t)l * 8 * WSZ;
        const float* Bv = dec_attn_b + (size_t)l * 8 * D_MODEL;
        const float* lns = dec_ln_s + (size_t)l * 3 * D_MODEL;
        const float* lnb = dec_ln_b + (size_t)l * 3 * D_MODEL;
        gemm(y, W + 0 * WSZ, Bv + 0 * D_MODEL, q, NTOK, D_MODEL, D_MODEL, 0);
        gemm(y, W + 1 * WSZ, Bv + 1 * D_MODEL, k, NTOK, D_MODEL, D_MODEL, 0);
        gemm(y, W + 2 * WSZ, Bv + 2 * D_MODEL, v, NTOK, D_MODEL, D_MODEL, 0);
        attn_score_kernel<<<sc_grid, 256>>>(q, k, nullptr, tgt, s);
        softmax_kernel<<<sm_grid, 256>>>(s);
        attn_av_kernel<<<av_grid, 256>>>(s, v, t);
        gemm(t, W + 3 * WSZ, Bv + 3 * D_MODEL, q, NTOK, D_MODEL, D_MODEL, 0);
        ln_kernel<<<NTOK, 256>>>(q, y, lns + 0 * D_MODEL, lnb + 0 * D_MODEL, y);
        gemm(y, W + 4 * WSZ, Bv + 4 * D_MODEL, q, NTOK, D_MODEL, D_MODEL, 0);
        gemm(x, W + 5 * WSZ, Bv + 5 * D_MODEL, k, NTOK, D_MODEL, D_MODEL, 0);
        gemm(x, W + 6 * WSZ, Bv + 6 * D_MODEL, v, NTOK, D_MODEL, D_MODEL, 0);
        attn_score_kernel<<<sc_grid, 256>>>(q, k, src, nullptr, s);
        softmax_kernel<<<sm_grid, 256>>>(s);
        attn_av_kernel<<<av_grid, 256>>>(s, v, t);
        gemm(t, W + 7 * WSZ, Bv + 7 * D_MODEL, q, NTOK, D_MODEL, D_MODEL, 0);
        ln_kernel<<<NTOK, 256>>>(q, y, lns + 1 * D_MODEL, lnb + 1 * D_MODEL, y);
        gemm(y, dec_ff_w1 + (size_t)l * D_MODEL * D_FF, dec_ff_b1 + (size_t)l * D_FF, ff,
             NTOK, D_FF, D_MODEL, 1);
        gemm(ff, dec_ff_w2 + (size_t)l * D_FF * D_MODEL, dec_ff_b2 + (size_t)l * D_MODEL, t,
             NTOK, D_MODEL, D_FF, 0);
        ln_kernel<<<NTOK, 256>>>(t, y, lns + 2 * D_MODEL, lnb + 2 * D_MODEL, y);
    }

    // ---------------- final projection ----------------
    gemm(y, fc_w, fc_b, out, NTOK, VOCAB, D_MODEL, 0);
}

// round 4
// speedup vs baseline: 3.8351x; 2.7832x over previous
#include <cuda_runtime.h>
#include <cuda_bf16.h>
#include <math.h>
#include <stdint.h>

#define D_MODEL 512
#define N_HEADS 8
#define DH 64
#define N_LAYERS 6
#define D_FF 2048
#define SEQ 512
#define BATCH 8
#define VOCAB 32000
#define NTOK (BATCH * SEQ)   /* 4096 */
#define NEGV (-1e9f)
#define TOKD ((size_t)NTOK * D_MODEL)

// ---------------- scratch (device globals; no runtime allocation) ----------------
__device__ float g_x[NTOK * D_MODEL];
__device__ float g_y[NTOK * D_MODEL];
__device__ float g_t[NTOK * D_MODEL];
__device__ float g_qkv[3 * NTOK * D_MODEL];
__device__ float g_kv[12 * NTOK * D_MODEL];
__device__ float g_ff[NTOK * D_FF];

// =================== HMMA bf16 helpers ===================
__device__ __forceinline__ void mma_bf16(float& d0, float& d1, float& d2, float& d3,
                                         uint32_t a0, uint32_t a1, uint32_t a2, uint32_t a3,
                                         uint32_t b0, uint32_t b1) {
    asm volatile(
        "mma.sync.aligned.m16n8k16.row.col.f32.bf16.bf16.f32 "
        "{%0,%1,%2,%3}, {%4,%5,%6,%7}, {%8,%9}, {%0,%1,%2,%3};\n"
        : "+f"(d0), "+f"(d1), "+f"(d2), "+f"(d3)
        : "r"(a0), "r"(a1), "r"(a2), "r"(a3), "r"(b0), "r"(b1));
}

__device__ __forceinline__ uint32_t bf16x3_pack(float x, float y, uint32_t& lo) {
    __nv_bfloat16 hx = __float2bfloat16(x), hy = __float2bfloat16(y);
    __nv_bfloat16 lx = __float2bfloat16(x - __bfloat162float(hx));
    __nv_bfloat16 ly = __float2bfloat16(y - __bfloat162float(hy));
    lo = ((uint32_t)__bfloat16_as_ushort(ly) << 16) | (uint32_t)__bfloat16_as_ushort(lx);
    return ((uint32_t)__bfloat16_as_ushort(hy) << 16) | (uint32_t)__bfloat16_as_ushort(hx);
}
__device__ __forceinline__ uint32_t lds_u32(const __nv_bfloat16* p) {
    return *(const uint32_t*)p;
}

// =================== HMMA GEMM (z-batched): C_z = A @ W_z + bias_z (+ReLU) ============
#define BM 128
#define BN 128
#define BK 32
#define STRA 40
#define STRB 34

__global__ __launch_bounds__(256, 2) void hmma_gemm_kernel(
    const float* __restrict__ A, const float* __restrict__ W,
    const float* __restrict__ bias, float* __restrict__ C,
    int M, int N, int K, int relu,
    int wdiv, long long ws1, long long ws2, long long bs1, long long bs2,
    long long cstride) {
    __shared__ __nv_bfloat16 sA_hi[BM * STRA];
    __shared__ __nv_bfloat16 sA_lo[BM * STRA];
    __shared__ __nv_bfloat16 sB_hi[BN * STRB];
    __shared__ __nv_bfloat16 sB_lo[BN * STRB];

    int z = blockIdx.z;
    W += (long long)(z / wdiv) * ws1 + (long long)(z % wdiv) * ws2;
    bias += (long long)(z / wdiv) * bs1 + (long long)(z % wdiv) * bs2;
    C += (size_t)z * (size_t)cstride;

    int tid = threadIdx.x, lane = tid & 31, w = tid >> 5;
    int wm = (w & 3) * 32, wn = (w >> 2) * 64;
    int g = lane >> 2, t = lane & 3;
    int bm = blockIdx.y * BM, bn = blockIdx.x * BN;

    float d[2][8][4];
#pragma unroll
    for (int mt = 0; mt < 2; mt++)
#pragma unroll
        for (int nt = 0; nt < 8; nt++)
#pragma unroll
            for (int e = 0; e < 4; e++) d[mt][nt][e] = 0.f;

    for (int kc = 0; kc < K; kc += BK) {
#pragma unroll
        for (int i = 0; i < 4; i++) {
            int idx = i * 256 + tid;
            int r = idx >> 3, q = idx & 7;
            float4 v = *(const float4*)(A + (size_t)(bm + r) * K + kc + q * 4);
            uint32_t lo0, lo1;
            uint32_t hi0 = bf16x3_pack(v.x, v.y, lo0);
            uint32_t hi1 = bf16x3_pack(v.z, v.w, lo1);
            uint32_t* ph = (uint32_t*)&sA_hi[r * STRA + q * 4];
            uint32_t* pl = (uint32_t*)&sA_lo[r * STRA + q * 4];
            ph[0] = hi0; ph[1] = hi1;
            pl[0] = lo0; pl[1] = lo1;
        }
#pragma unroll
        for (int it = 0; it < 2; it++) {
            int idx = it * 256 + tid;
            int kp = idx >> 5;
            int nq = (idx & 31) * 4;
            const float* w0 = W + (size_t)(kc + 2 * kp) * N + bn + nq;
            float4 v0 = *(const float4*)w0;
            float4 v1 = *(const float4*)(w0 + N);
            float x0[4] = {v0.x, v0.y, v0.z, v0.w};
            float x1[4] = {v1.x, v1.y, v1.z, v1.w};
#pragma unroll
            for (int j = 0; j < 4; j++) {
                uint32_t lo;
                uint32_t hi = bf16x3_pack(x0[j], x1[j], lo);
                *(uint32_t*)&sB_hi[(nq + j) * STRB + 2 * kp] = hi;
                *(uint32_t*)&sB_lo[(nq + j) * STRB + 2 * kp] = lo;
            }
        }
        __syncthreads();

#pragma unroll
        for (int ks = 0; ks < 2; ks++) {
            int k0 = ks * 16;
            uint32_t ah[2][4], al[2][4];
#pragma unroll
            for (int mt = 0; mt < 2; mt++) {
                int row = wm + mt * 16 + g;
                const __nv_bfloat16* pa = &sA_hi[row * STRA + k0 + 2 * t];
                ah[mt][0] = lds_u32(pa);
                ah[mt][1] = lds_u32(pa + 8 * STRA);
                ah[mt][2] = lds_u32(pa + 8);
                ah[mt][3] = lds_u32(pa + 8 * STRA + 8);
                const __nv_bfloat16* pl = &sA_lo[row * STRA + k0 + 2 * t];
                al[mt][0] = lds_u32(pl);
                al[mt][1] = lds_u32(pl + 8 * STRA);
                al[mt][2] = lds_u32(pl + 8);
                al[mt][3] = lds_u32(pl + 8 * STRA + 8);
            }
#pragma unroll
            for (int nt = 0; nt < 8; nt++) {
                int col = wn + nt * 8 + g;
                const __nv_bfloat16* pb = &sB_hi[col * STRB + k0 + 2 * t];
                uint32_t bh0 = lds_u32(pb);
                uint32_t bh1 = lds_u32(pb + 8);
                const __nv_bfloat16* pbl = &sB_lo[col * STRB + k0 + 2 * t];
                uint32_t bl0 = lds_u32(pbl);
                uint32_t bl1 = lds_u32(pbl + 8);
#pragma unroll
                for (int mt = 0; mt < 2; mt++) {
                    mma_bf16(d[mt][nt][0], d[mt][nt][1], d[mt][nt][2], d[mt][nt][3],
                             ah[mt][0], ah[mt][1], ah[mt][2], ah[mt][3], bh0, bh1);
                    mma_bf16(d[mt][nt][0], d[mt][nt][1], d[mt][nt][2], d[mt][nt][3],
                             ah[mt][0], ah[mt][1], ah[mt][2], ah[mt][3], bl0, bl1);
                    mma_bf16(d[mt][nt][0], d[mt][nt][1], d[mt][nt][2], d[mt][nt][3],
                             al[mt][0], al[mt][1], al[mt][2], al[mt][3], bh0, bh1);
                }
            }
        }
        __syncthreads();
    }

#pragma unroll
    for (int mt = 0; mt < 2; mt++) {
        int r0 = bm + wm + mt * 16 + g;
#pragma unroll
        for (int nt = 0; nt < 8; nt++) {
            int col = bn + wn + nt * 8 + 2 * t;
            float b0 = bias[col], b1 = bias[col + 1];
            float v0 = d[mt][nt][0] + b0, v1 = d[mt][nt][1] + b1;
            float v2 = d[mt][nt][2] + b0, v3 = d[mt][nt][3] + b1;
            if (relu) {
                v0 = fmaxf(v0, 0.f); v1 = fmaxf(v1, 0.f);
                v2 = fmaxf(v2, 0.f); v3 = fmaxf(v3, 0.f);
            }
            *(float2*)(C + (size_t)r0 * N + col) = make_float2(v0, v1);
            *(float2*)(C + (size_t)(r0 + 8) * N + col) = make_float2(v2, v3);
        }
    }
}

// =================== fused flash attention ===================
// grid (8 i-tiles, 64 b*h), block 128 (4 warps x 16 rows). DH=64.
// kmask_tok: key padding mask (src tokens) or null. qtok: causal + query pad (tgt) or null.
#define FSTR 72
#define FA_TILE_BYTES (64 * FSTR * 2)
#define FA_SMEM (6 * FA_TILE_BYTES + 64 * 4 + 16)

__global__ __launch_bounds__(128) void flash_kernel(
    const float* __restrict__ Q, const float* __restrict__ K, const float* __restrict__ V,
    float* __restrict__ O, const int* __restrict__ kmask_tok, const int* __restrict__ qtok) {
    extern __shared__ char fsm[];
    __nv_bfloat16* sQh = (__nv_bfloat16*)fsm;
    __nv_bfloat16* sQl = sQh + 64 * FSTR;
    __nv_bfloat16* sKh = sQl + 64 * FSTR;
    __nv_bfloat16* sKl = sKh + 64 * FSTR;
    __nv_bfloat16* sVh = sKl + 64 * FSTR;   // transposed [d][j]
    __nv_bfloat16* sVl = sVh + 64 * FSTR;
    float* sMask = (float*)(sVl + 64 * FSTR);
    int* sAll = (int*)(sMask + 64);

    int tid = threadIdx.x, lane = tid & 31, w = tid >> 5;
    int g = lane >> 2, t = lane & 3;
    int it = blockIdx.x, bh = blockIdx.y;
    int b = bh >> 3, h = bh & 7;
    int i0 = it * 64;
    int wm = w * 16;

    const float* qbase = Q + ((size_t)(b * SEQ + i0)) * D_MODEL + h * DH;
    const float* kbase0 = K + ((size_t)(b * SEQ)) * D_MODEL + h * DH;
    const float* vbase0 = V + ((size_t)(b * SEQ)) * D_MODEL + h * DH;

    if (tid == 0) *sAll = 1;
    __syncthreads();

    // stage Q tile (64x64), hi/lo split
#pragma unroll
    for (int i = 0; i < 8; i++) {
        int idx = i * 128 + tid;
        int r = idx >> 4, q4 = (idx & 15) * 4;
        float4 v = *(const float4*)(qbase + (size_t)r * D_MODEL + q4);
        uint32_t lo0, lo1;
        uint32_t hi0 = bf16x3_pack(v.x, v.y, lo0);
        uint32_t hi1 = bf16x3_pack(v.z, v.w, lo1);
        *(uint32_t*)&sQh[r * FSTR + q4] = hi0;
        *(uint32_t*)&sQh[r * FSTR + q4 + 2] = hi1;
        *(uint32_t*)&sQl[r * FSTR + q4] = lo0;
        *(uint32_t*)&sQl[r * FSTR + q4 + 2] = lo1;
    }

    bool causal = (qtok != nullptr);
    int qv0 = 1, qv1 = 1;
    if (causal) {
        qv0 = (qtok[b * SEQ + i0 + wm + g] != 0);
        qv1 = (qtok[b * SEQ + i0 + wm + g + 8] != 0);
        if (tid < 64 && qtok[b * SEQ + i0 + tid] == 0) *sAll = 0;
    }
    __syncthreads();
    int njt = causal ? ((*sAll) ? (it + 1) : 8) : 8;

    float m0 = -1e30f, m1 = -1e30f, l0 = 0.f, l1 = 0.f;
    float o[8][4];
#pragma unroll
    for (int nt = 0; nt < 8; nt++)
#pragma unroll
        for (int e = 0; e < 4; e++) o[nt][e] = 0.f;

    int irow0 = i0 + wm + g;
    int irow1 = irow0 + 8;

    for (int jt = 0; jt < njt; jt++) {
        int j0 = jt * 64;
        const float* kb = kbase0 + (size_t)j0 * D_MODEL;
        const float* vb = vbase0 + (size_t)j0 * D_MODEL;
        // stage K (64x64) hi/lo
#pragma unroll
        for (int i = 0; i < 8; i++) {
            int idx = i * 128 + tid;
            int r = idx >> 4, q4 = (idx & 15) * 4;
            float4 v = *(const float4*)(kb + (size_t)r * D_MODEL + q4);
            uint32_t lo0, lo1;
            uint32_t hi0 = bf16x3_pack(v.x, v.y, lo0);
            uint32_t hi1 = bf16x3_pack(v.z, v.w, lo1);
            *(uint32_t*)&sKh[r * FSTR + q4] = hi0;
            *(uint32_t*)&sKh[r * FSTR + q4 + 2] = hi1;
            *(uint32_t*)&sKl[r * FSTR + q4] = lo0;
            *(uint32_t*)&sKl[r * FSTR + q4 + 2] = lo1;
        }
        // stage V transposed: sV[d][j], j-pairs packed
#pragma unroll
        for (int i = 0; i < 4; i++) {
            int idx = i * 128 + tid;
            int jp = idx >> 4, dq = (idx & 15) * 4;
            const float* p0 = vb + (size_t)(2 * jp) * D_MODEL + dq;
            float4 a = *(const float4*)p0;
            float4 c = *(const float4*)(p0 + D_MODEL);
            float ax[4] = {a.x, a.y, a.z, a.w};
            float cx[4] = {c.x, c.y, c.z, c.w};
#pragma unroll
            for (int e = 0; e < 4; e++) {
                uint32_t lo;
                uint32_t hi = bf16x3_pack(ax[e], cx[e], lo);
                *(uint32_t*)&sVh[(dq + e) * FSTR + 2 * jp] = hi;
                *(uint32_t*)&sVl[(dq + e) * FSTR + 2 * jp] = lo;
            }
        }
        if (kmask_tok && tid < 64)
            sMask[tid] = (kmask_tok[b * SEQ + j0 + tid] != 0) ? 0.f : NEGV;
        __syncthreads();

        // ---- S = Q K^T (bf16x3) ----
        float s[8][4];
#pragma unroll
        for (int nt = 0; nt < 8; nt++)
#pragma unroll
            for (int e = 0; e < 4; e++) s[nt][e] = 0.f;
#pragma unroll
        for (int kk = 0; kk < 4; kk++) {
            int k0 = kk * 16;
            const __nv_bfloat16* pa = &sQh[(wm + g) * FSTR + k0 + 2 * t];
            uint32_t ah0 = lds_u32(pa), ah1 = lds_u32(pa + 8 * FSTR);
            uint32_t ah2 = lds_u32(pa + 8), ah3 = lds_u32(pa + 8 * FSTR + 8);
            const __nv_bfloat16* pal = &sQl[(wm + g) * FSTR + k0 + 2 * t];
            uint32_t al0 = lds_u32(pal), al1 = lds_u32(pal + 8 * FSTR);
            uint32_t al2 = lds_u32(pal + 8), al3 = lds_u32(pal + 8 * FSTR + 8);
#pragma unroll
            for (int nt = 0; nt < 8; nt++) {
                const __nv_bfloat16* pb = &sKh[(nt * 8 + g) * FSTR + k0 + 2 * t];
                uint32_t bh0 = lds_u32(pb), bh1 = lds_u32(pb + 8);
                const __nv_bfloat16* pbl = &sKl[(nt * 8 + g) * FSTR + k0 + 2 * t];
                uint32_t bl0 = lds_u32(pbl), bl1 = lds_u32(pbl + 8);
                mma_bf16(s[nt][0], s[nt][1], s[nt][2], s[nt][3], ah0, ah1, ah2, ah3, bh0, bh1);
                mma_bf16(s[nt][0], s[nt][1], s[nt][2], s[nt][3], ah0, ah1, ah2, ah3, bl0, bl1);
                mma_bf16(s[nt][0], s[nt][1], s[nt][2], s[nt][3], al0, al1, al2, al3, bh0, bh1);
            }
        }
        // ---- scale + mask ----
        if (causal) {
#pragma unroll
            for (int nt = 0; nt < 8; nt++) {
                int c0 = j0 + nt * 8 + 2 * t, c1 = c0 + 1;
                s[nt][0] = (qv0 && c0 <= irow0) ? s[nt][0] * 0.125f : NEGV;
                s[nt][1] = (qv0 && c1 <= irow0) ? s[nt][1] * 0.125f : NEGV;
                s[nt][2] = (qv1 && c0 <= irow1) ? s[nt][2] * 0.125f : NEGV;
                s[nt][3] = (qv1 && c1 <= irow1) ? s[nt][3] * 0.125f : NEGV;
            }
        } else {
#pragma unroll
            for (int nt = 0; nt < 8; nt++) {
                int cc = nt * 8 + 2 * t;
                bool v0 = (sMask[cc] == 0.f), v1 = (sMask[cc + 1] == 0.f);
                s[nt][0] = v0 ? s[nt][0] * 0.125f : NEGV;
                s[nt][1] = v1 ? s[nt][1] * 0.125f : NEGV;
                s[nt][2] = v0 ? s[nt][2] * 0.125f : NEGV;
                s[nt][3] = v1 ? s[nt][3] * 0.125f : NEGV;
            }
        }
        // ---- online softmax ----
        float rm0 = -1e30f, rm1 = -1e30f;
#pragma unroll
        for (int nt = 0; nt < 8; nt++) {
            rm0 = fmaxf(rm0, fmaxf(s[nt][0], s[nt][1]));
            rm1 = fmaxf(rm1, fmaxf(s[nt][2], s[nt][3]));
        }
        rm0 = fmaxf(rm0, __shfl_xor_sync(0xffffffffu, rm0, 1));
        rm0 = fmaxf(rm0, __shfl_xor_sync(0xffffffffu, rm0, 2));
        rm1 = fmaxf(rm1, __shfl_xor_sync(0xffffffffu, rm1, 1));
        rm1 = fmaxf(rm1, __shfl_xor_sync(0xffffffffu, rm1, 2));
        float nm0 = fmaxf(m0, rm0), nm1 = fmaxf(m1, rm1);
        float f0 = __expf(m0 - nm0), f1 = __expf(m1 - nm1);
        float rs0 = 0.f, rs1 = 0.f;
#pragma unroll
        for (int nt = 0; nt < 8; nt++) {
            s[nt][0] = __expf(s[nt][0] - nm0);
            s[nt][1] = __expf(s[nt][1] - nm0);
            s[nt][2] = __expf(s[nt][2] - nm1);
            s[nt][3] = __expf(s[nt][3] - nm1);
            rs0 += s[nt][0] + s[nt][1];
            rs1 += s[nt][2] + s[nt][3];
        }
        rs0 += __shfl_xor_sync(0xffffffffu, rs0, 1);
        rs0 += __shfl_xor_sync(0xffffffffu, rs0, 2);
        rs1 += __shfl_xor_sync(0xffffffffu, rs1, 1);
        rs1 += __shfl_xor_sync(0xffffffffu, rs1, 2);
        l0 = l0 * f0 + rs0;
        l1 = l1 * f1 + rs1;
        m0 = nm0; m1 = nm1;
#pragma unroll
        for (int nt = 0; nt < 8; nt++) {
            o[nt][0] *= f0; o[nt][1] *= f0;
            o[nt][2] *= f1; o[nt][3] *= f1;
        }
        // ---- O += P V (bf16x3) ----
#pragma unroll
        for (int kk = 0; kk < 4; kk++) {
            uint32_t pl0, pl1, pl2, pl3;
            uint32_t ph0 = bf16x3_pack(s[2 * kk][0], s[2 * kk][1], pl0);
            uint32_t ph1 = bf16x3_pack(s[2 * kk][2], s[2 * kk][3], pl1);
            uint32_t ph2 = bf16x3_pack(s[2 * kk + 1][0], s[2 * kk + 1][1], pl2);
            uint32_t ph3 = bf16x3_pack(s[2 * kk + 1][2], s[2 * kk + 1][3], pl3);
            int k0 = kk * 16;
#pragma unroll
            for (int nt = 0; nt < 8; nt++) {
                const __nv_bfloat16* pb = &sVh[(nt * 8 + g) * FSTR + k0 + 2 * t];
                uint32_t bh0 = lds_u32(pb), bh1 = lds_u32(pb + 8);
                const __nv_bfloat16* pbl = &sVl[(nt * 8 + g) * FSTR + k0 + 2 * t];
                uint32_t bl0 = lds_u32(pbl), bl1 = lds_u32(pbl + 8);
                mma_bf16(o[nt][0], o[nt][1], o[nt][2], o[nt][3], ph0, ph1, ph2, ph3, bh0, bh1);
                mma_bf16(o[nt][0], o[nt][1], o[nt][2], o[nt][3], ph0, ph1, ph2, ph3, bl0, bl1);
                mma_bf16(o[nt][0], o[nt][1], o[nt][2], o[nt][3], pl0, pl1, pl2, pl3, bh0, bh1);
            }
        }
        __syncthreads();
    }
    // ---- epilogue ----
    float inv0 = 1.f / l0, inv1 = 1.f / l1;
    float* ob0 = O + ((size_t)(b * SEQ) + irow0) * D_MODEL + h * DH;
    float* ob1 = O + ((size_t)(b * SEQ) + irow1) * D_MODEL + h * DH;
#pragma unroll
    for (int nt = 0; nt < 8; nt++) {
        int d0 = nt * 8 + 2 * t;
        *(float2*)(ob0 + d0) = make_float2(o[nt][0] * inv0, o[nt][1] * inv0);
        *(float2*)(ob1 + d0) = make_float2(o[nt][2] * inv1, o[nt][3] * inv1);
    }
}

// ---------------- embedding + positional encoding ----------------
__global__ void embed_kernel(const int* __restrict__ tok, const float* __restrict__ emb,
                             float* __restrict__ out) {
    int row = blockIdx.x;
    int s = row % SEQ;
    int t = tok[row];
    const float scale = 22.627416997969522f;
    const float c = -9.210340371976184f / 512.0f;
    for (int d = threadIdx.x; d < D_MODEL; d += blockDim.x) {
        int i2 = d & ~1;
        float div = expf((float)i2 * c);
        float ang = (float)s * div;
        float pe = (d & 1) ? cosf(ang) : sinf(ang);
        out[row * D_MODEL + d] = emb[(size_t)t * D_MODEL + d] * scale + pe;
    }
}

// ---------------- fused residual-add + LayerNorm ----------------
__global__ void ln_kernel(const float* __restrict__ A, const float* __restrict__ R,
                          const float* __restrict__ sc, const float* __restrict__ bi,
                          float* __restrict__ out) {
    int row = blockIdx.x, tid = threadIdx.x;
    size_t base = (size_t)row * D_MODEL;
    float x0 = A[base + tid] + R[base + tid];
    float x1 = A[base + tid + 256] + R[base + tid + 256];
    __shared__ float red[8];
    float ssum = x0 + x1;
#pragma unroll
    for (int o = 16; o; o >>= 1) ssum += __shfl_xor_sync(0xffffffffu, ssum, o);
    if ((tid & 31) == 0) red[tid >> 5] = ssum;
    __syncthreads();
    float tot = red[0];
#pragma unroll
    for (int i = 1; i < 8; i++) tot += red[i];
    float mean = tot * (1.0f / D_MODEL);
    __syncthreads();
    float d0 = x0 - mean, d1 = x1 - mean;
    float vsum = d0 * d0 + d1 * d1;
#pragma unroll
    for (int o = 16; o; o >>= 1) vsum += __shfl_xor_sync(0xffffffffu, vsum, o);
    if ((tid & 31) == 0) red[tid >> 5] = vsum;
    __syncthreads();
    float vtot = red[0];
#pragma unroll
    for (int i = 1; i < 8; i++) vtot += red[i];
    float inv = rsqrtf(vtot * (1.0f / D_MODEL) + 1e-5f);
    out[base + tid] = d0 * inv * sc[tid] + bi[tid];
    out[base + tid + 256] = d1 * inv * sc[tid + 256] + bi[tid + 256];
}

// ---------------- host orchestration ----------------
static inline void gemm(const float* A, const float* W, const float* bias, float* C,
                        int M, int N, int K, int relu,
                        int G = 1, int wdiv = 1, long long ws1 = 0, long long ws2 = 0,
                        long long bs1 = 0, long long bs2 = 0, long long cstride = 0) {
    dim3 grid(N / BN, M / BM, G);
    hmma_gemm_kernel<<<grid, 256>>>(A, W, bias, C, M, N, K, relu,
                                    wdiv, ws1, ws2, bs1, bs2, cstride);
}

extern "C" void kernel_launch(void* const* d_in, const int* in_sizes, int n_in,
                              void* d_out, int out_size) {
    const int* src = (const int*)d_in[0];
    const int* tgt = (const int*)d_in[1];
    const float* src_emb = (const float*)d_in[2];
    const float* tgt_emb = (const float*)d_in[3];
    const float* enc_attn_w = (const float*)d_in[4];
    const float* enc_attn_b = (const float*)d_in[5];
    const float* enc_ln_s = (const float*)d_in[6];
    const float* enc_ln_b = (const float*)d_in[7];
    const float* enc_ff_w1 = (const float*)d_in[8];
    const float* enc_ff_b1 = (const float*)d_in[9];
    const float* enc_ff_w2 = (const float*)d_in[10];
    const float* enc_ff_b2 = (const float*)d_in[11];
    const float* dec_attn_w = (const float*)d_in[12];
    const float* dec_attn_b = (const float*)d_in[13];
    const float* dec_ln_s = (const float*)d_in[14];
    const float* dec_ln_b = (const float*)d_in[15];
    const float* dec_ff_w1 = (const float*)d_in[16];
    const float* dec_ff_b1 = (const float*)d_in[17];
    const float* dec_ff_w2 = (const float*)d_in[18];
    const float* dec_ff_b2 = (const float*)d_in[19];
    const float* fc_w = (const float*)d_in[20];
    const float* fc_b = (const float*)d_in[21];
    float* out = (float*)d_out;

    cudaFuncSetAttribute(flash_kernel, cudaFuncAttributeMaxDynamicSharedMemorySize, FA_SMEM);

    float *x, *y, *t, *qkv, *kv, *ff;
    cudaGetSymbolAddress((void**)&x, g_x);
    cudaGetSymbolAddress((void**)&y, g_y);
    cudaGetSymbolAddress((void**)&t, g_t);
    cudaGetSymbolAddress((void**)&qkv, g_qkv);
    cudaGetSymbolAddress((void**)&kv, g_kv);
    cudaGetSymbolAddress((void**)&ff, g_ff);
    float* q = qkv;
    float* k = qkv + TOKD;
    float* v = qkv + 2 * TOKD;

    const dim3 fa_grid(SEQ / 64, BATCH * N_HEADS);
    const size_t WSZ = (size_t)D_MODEL * D_MODEL;

    // ---------------- encoder ----------------
    embed_kernel<<<NTOK, 256>>>(src, src_emb, x);
    for (int l = 0; l < N_LAYERS; l++) {
        const float* W = enc_attn_w + (size_t)l * 4 * WSZ;
        const float* Bv = enc_attn_b + (size_t)l * 4 * D_MODEL;
        gemm(x, W, Bv, qkv, NTOK, D_MODEL, D_MODEL, 0,
             3, 4, 0, (long long)WSZ, 0, D_MODEL, (long long)TOKD);
        flash_kernel<<<fa_grid, 128, FA_SMEM>>>(q, k, v, t, src, nullptr);
        gemm(t, W + 3 * WSZ, Bv + 3 * D_MODEL, q, NTOK, D_MODEL, D_MODEL, 0);
        ln_kernel<<<NTOK, 256>>>(q, x, enc_ln_s + (size_t)(l * 2 + 0) * D_MODEL,
                                 enc_ln_b + (size_t)(l * 2 + 0) * D_MODEL, x);
        gemm(x, enc_ff_w1 + (size_t)l * D_MODEL * D_FF, enc_ff_b1 + (size_t)l * D_FF, ff,
             NTOK, D_FF, D_MODEL, 1);
        gemm(ff, enc_ff_w2 + (size_t)l * D_FF * D_MODEL, enc_ff_b2 + (size_t)l * D_MODEL, t,
             NTOK, D_MODEL, D_FF, 0);
        ln_kernel<<<NTOK, 256>>>(t, x, enc_ln_s + (size_t)(l * 2 + 1) * D_MODEL,
                                 enc_ln_b + (size_t)(l * 2 + 1) * D_MODEL, x);
    }

    // ---- all 12 decoder cross K/V projections in one batched launch ----
    gemm(x, dec_attn_w + 5 * WSZ, dec_attn_b + 5 * D_MODEL, kv, NTOK, D_MODEL, D_MODEL, 0,
         12, 2, (long long)(8 * WSZ), (long long)WSZ,
         8LL * D_MODEL, D_MODEL, (long long)TOKD);

    // ---------------- decoder ----------------
    embed_kernel<<<NTOK, 256>>>(tgt, tgt_emb, y);
    for (int l = 0; l < N_LAYERS; l++) {
        const float* W = dec_attn_w + (size_t)l * 8 * WSZ;
        const float* Bv = dec_attn_b + (size_t)l * 8 * D_MODEL;
        const float* lns = dec_ln_s + (size_t)l * 3 * D_MODEL;
        const float* lnb = dec_ln_b + (size_t)l * 3 * D_MODEL;
        // self-attn (causal + tgt pad)
        gemm(y, W, Bv, qkv, NTOK, D_MODEL, D_MODEL, 0,
             3, 4, 0, (long long)WSZ, 0, D_MODEL, (long long)TOKD);
        flash_kernel<<<fa_grid, 128, FA_SMEM>>>(q, k, v, t, nullptr, tgt);
        gemm(t, W + 3 * WSZ, Bv + 3 * D_MODEL, q, NTOK, D_MODEL, D_MODEL, 0);
        ln_kernel<<<NTOK, 256>>>(q, y, lns + 0 * D_MODEL, lnb + 0 * D_MODEL, y);
        // cross-attn (K/V precomputed in kv)
        gemm(y, W + 4 * WSZ, Bv + 4 * D_MODEL, q, NTOK, D_MODEL, D_MODEL, 0);
        flash_kernel<<<fa_grid, 128, FA_SMEM>>>(q, kv + (size_t)(2 * l) * TOKD,
                                                kv + (size_t)(2 * l + 1) * TOKD, t, src, nullptr);
        gemm(t, W + 7 * WSZ, Bv + 7 * D_MODEL, k, NTOK, D_MODEL, D_MODEL, 0);
        ln_kernel<<<NTOK, 256>>>(k, y, lns + 1 * D_MODEL, lnb + 1 * D_MODEL, y);
        // ffn
        gemm(y, dec_ff_w1 + (size_t)l * D_MODEL * D_FF, dec_ff_b1 + (size_t)l * D_FF, ff,
             NTOK, D_FF, D_MODEL, 1);
        gemm(ff, dec_ff_w2 + (size_t)l * D_FF * D_MODEL, dec_ff_b2 + (size_t)l * D_MODEL, t,
             NTOK, D_MODEL, D_FF, 0);
        ln_kernel<<<NTOK, 256>>>(t, y, lns + 2 * D_MODEL, lnb + 2 * D_MODEL, y);
    }

    // ---------------- final projection ----------------
    gemm(y, fc_w, fc_b, out, NTOK, VOCAB, D_MODEL, 0);
}